// round 1
// baseline (speedup 1.0000x reference)
#include <cuda_runtime.h>

// Problem constants (fixed by setup_inputs): x[32, 336, 32, 32] fp32, k=25, pe=24
#define BB   32
#define CC   336
#define HWW  1024
#define KS   25
#define PE   24
#define NG   (CC / PE)          // 14 groups
#define NCOL (BB * HWW)         // 32768 independent columns
#define NELEM ((size_t)BB * CC * HWW)

__global__ __launch_bounds__(128)
void decomp_kernel(const float* __restrict__ x,
                   float* __restrict__ To,
                   float* __restrict__ So,
                   float* __restrict__ Ro)
{
    int col = blockIdx.x * blockDim.x + threadIdx.x;
    if (col >= NCOL) return;
    int b  = col >> 10;          // col / 1024
    int hw = col & (HWW - 1);    // col % 1024

    const size_t base = (size_t)b * CC * HWW + hw;
    const float* __restrict__ xp = x + base;

    const float inv_k = 1.0f / (float)KS;
    const float inv_g = 1.0f / (float)NG;

    // Initial window sum for c=0: padded window = 13 copies of x[0] + x[1..12]
    float x0 = xp[0];
    float wsum0 = 13.0f * x0;
    #pragma unroll
    for (int j = 1; j <= 12; j++) wsum0 += xp[(size_t)j * HWW];

    // ---------------- Pass A: trend T + per-phase sums of detrended ----------------
    float pacc[PE];
    #pragma unroll
    for (int p = 0; p < PE; p++) pacc[p] = 0.0f;

    float wsum = wsum0;
    for (int g = 0; g < NG; g++) {
        #pragma unroll
        for (int p = 0; p < PE; p++) {
            const int c = g * PE + p;
            float T  = wsum * inv_k;
            float xc = xp[(size_t)c * HWW];
            To[base + (size_t)c * HWW] = T;
            pacc[p] += xc - T;
            // slide window: +x[clamp(c+13)] - x[clamp(c-12)]
            int cin  = c + 13; if (cin  > CC - 1) cin  = CC - 1;
            int cout = c - 12; if (cout < 0)      cout = 0;
            wsum += xp[(size_t)cin * HWW] - xp[(size_t)cout * HWW];
        }
    }

    #pragma unroll
    for (int p = 0; p < PE; p++) pacc[p] *= inv_g;   // seasonal means

    // ---------------- Pass B: recompute identical T, emit S and R ----------------
    wsum = wsum0;
    for (int g = 0; g < NG; g++) {
        #pragma unroll
        for (int p = 0; p < PE; p++) {
            const int c = g * PE + p;
            float T  = wsum * inv_k;
            float xc = xp[(size_t)c * HWW];   // L2 hit (x < L2 capacity)
            float S  = pacc[p];
            float xd = xc - T;
            So[base + (size_t)c * HWW] = S;
            Ro[base + (size_t)c * HWW] = xd - S;
            int cin  = c + 13; if (cin  > CC - 1) cin  = CC - 1;
            int cout = c - 12; if (cout < 0)      cout = 0;
            wsum += xp[(size_t)cin * HWW] - xp[(size_t)cout * HWW];
        }
    }
}

extern "C" void kernel_launch(void* const* d_in, const int* in_sizes, int n_in,
                              void* d_out, int out_size)
{
    const float* x = (const float*)d_in[0];
    float* out = (float*)d_out;
    // Output tuple (T, S, R) concatenated
    float* To = out;
    float* So = out + NELEM;
    float* Ro = out + 2 * NELEM;
    decomp_kernel<<<NCOL / 128, 128>>>(x, To, So, Ro);
}

// round 2
// speedup vs baseline: 3.5763x; 3.5763x over previous
#include <cuda_runtime.h>

// x[32, 336, 32, 32] fp32, moving-avg k=25 (replicate pad), seasonal period 24
#define BB    32
#define CC    336
#define KS    25
#define PE    24
#define NG    (CC / PE)          // 14
#define HWW   1024
#define NCOL  (BB * HWW)         // 32768
#define NELEM ((size_t)BB * CC * HWW)

#define COLS_PER_BLK 32          // columns per block
#define THREADS (COLS_PER_BLK * NG)  // 448

__global__ __launch_bounds__(THREADS, 2)
void decomp_kernel(const float* __restrict__ x,
                   float* __restrict__ To,
                   float* __restrict__ So,
                   float* __restrict__ Ro)
{
    __shared__ float acc[COLS_PER_BLK][PE + 1];   // +1 pad: stride 25 coprime w/ 32 banks

    const int tx = threadIdx.x;          // column lane [0,32)
    const int g  = threadIdx.y;          // group      [0,14)
    const int col = blockIdx.x * COLS_PER_BLK + tx;
    const int b  = col >> 10;
    const int hw = col & (HWW - 1);

    const size_t base = (size_t)b * CC * HWW + hw;
    const float* __restrict__ xp = x + base;

    const float inv_k = 1.0f / (float)KS;
    const float inv_g = 1.0f / (float)NG;
    const int   c0    = g * PE;

    // zero the reduction buffer
    {
        int lin = threadIdx.y * COLS_PER_BLK + threadIdx.x;
        float* s = &acc[0][0];
        for (int i = lin; i < COLS_PER_BLK * (PE + 1); i += THREADS) s[i] = 0.0f;
    }

    // initial window sum at c = c0: sum_{j=-12..12} x[clamp(c0+j)]
    float wsum = 0.0f;
    #pragma unroll
    for (int j = -12; j <= 12; j++) {
        int cc = c0 + j;
        cc = cc < 0 ? 0 : (cc > CC - 1 ? CC - 1 : cc);
        wsum += xp[(size_t)cc * HWW];
    }

    // trend + detrended for this thread's 24 channels (kept in registers)
    float xd[PE];
    #pragma unroll
    for (int p = 0; p < PE; p++) {
        const int c = c0 + p;
        float T  = wsum * inv_k;
        float xc = xp[(size_t)c * HWW];
        To[base + (size_t)c * HWW] = T;
        xd[p] = xc - T;
        int cin  = c + 13; if (cin  > CC - 1) cin  = CC - 1;
        int cout = c - 12; if (cout < 0)      cout = 0;
        wsum += xp[(size_t)cin * HWW] - xp[(size_t)cout * HWW];
    }

    __syncthreads();

    // cross-group reduction in shared memory (conflict-free: 32 lanes -> 32 banks)
    #pragma unroll
    for (int p = 0; p < PE; p++)
        atomicAdd(&acc[tx][p], xd[p]);

    __syncthreads();

    // emit seasonal + residual from registers (no recompute pass)
    #pragma unroll
    for (int p = 0; p < PE; p++) {
        const int c = c0 + p;
        float S = acc[tx][p] * inv_g;
        So[base + (size_t)c * HWW] = S;
        Ro[base + (size_t)c * HWW] = xd[p] - S;
    }
}

extern "C" void kernel_launch(void* const* d_in, const int* in_sizes, int n_in,
                              void* d_out, int out_size)
{
    const float* x = (const float*)d_in[0];
    float* out = (float*)d_out;
    float* To = out;
    float* So = out + NELEM;
    float* Ro = out + 2 * NELEM;
    dim3 blk(COLS_PER_BLK, NG);
    decomp_kernel<<<NCOL / COLS_PER_BLK, blk>>>(x, To, So, Ro);
}